// round 5
// baseline (speedup 1.0000x reference)
#include <cuda_runtime.h>
#include <math.h>

#define N_BOXES 256
#define N_VIEWS 6
#define P_TOT   (N_BOXES * N_VIEWS)   // 1536
#define C_FEAT  256
#define HF      116
#define WF      200
#define HW      (HF * WF)             // 23200
#define EPS     1e-8f

#define NBLK    96                    // 96 blocks x 16 warps x 1 pair = 1536
#define NTHR    512
#define NWARP   16
#define FSCALE  4294967296.0          // 2^32 fixed-point scale

// Deterministic cross-block accumulators (integer atomics only)
__device__ unsigned long long g_sum  = 0ULL;
__device__ int                g_cnt  = 0;
__device__ int                g_done = 0;

__global__ void __launch_bounds__(NTHR, 1)
fused_kernel(const float* __restrict__ boxes,
             const float* __restrict__ feats,
             const float* __restrict__ Kmat,
             const float* __restrict__ Tmat,
             const int*   __restrict__ img_sizes,
             float*       __restrict__ out)
{
    __shared__ int   s_coord[P_TOT];      // u0c | v0c<<8 | valid<<31
    __shared__ int   s_first;
    __shared__ float s_stored[C_FEAT];
    __shared__ float s_red[256];
    __shared__ float s_sinv;
    __shared__ float s_loss[NWARP];
    __shared__ int   s_lval[NWARP];

    const int tid  = threadIdx.x;
    const int warp = tid >> 5;
    const int lane = tid & 31;

    if (tid == 0) s_first = P_TOT;
    __syncthreads();

    // ---- Phase 1: every block computes ALL projections (redundant, cheap) ----
    #pragma unroll
    for (int i = 0; i < P_TOT / NTHR; i++) {
        const int p = tid + i * NTHR;
        const int n = p / N_VIEWS;
        const int v = p - n * N_VIEWS;
        const float cx = boxes[n * 7 + 0];
        const float cy = boxes[n * 7 + 1];
        const float cz = boxes[n * 7 + 2];

        const float* Tv = Tmat + v * 16;   // 4x4 row-major
        const float pc0 = Tv[0] * cx + Tv[1] * cy + Tv[2]  * cz + Tv[3];
        const float pc1 = Tv[4] * cx + Tv[5] * cy + Tv[6]  * cz + Tv[7];
        const float pc2 = Tv[8] * cx + Tv[9] * cy + Tv[10] * cz + Tv[11];

        const float* Kv = Kmat + v * 9;    // 3x3 row-major
        const float q0 = Kv[0] * pc0 + Kv[1] * pc1 + Kv[2] * pc2;
        const float q1 = Kv[3] * pc0 + Kv[4] * pc1 + Kv[5] * pc2;
        const float q2 = Kv[6] * pc0 + Kv[7] * pc1 + Kv[8] * pc2;

        const float z  = pc2;
        const float u  = q0 / q2;          // ref: u = p2d.x / p2d.z
        const float vv = q1 / z;           // ref: v = p2d.y / p_cam.z

        const float Himg = (float)img_sizes[v * 2 + 0];
        const float Wimg = (float)img_sizes[v * 2 + 1];
        const float u_s = u  * (float)WF / Wimg;
        const float v_s = vv * (float)HF / Himg;
        const int u0 = (int)floorf(u_s);
        const int v0 = (int)floorf(v_s);

        const bool valid = (z > 0.0f) && (u >= 0.0f) && (u < Wimg) &&
                           (vv >= 0.0f) && (vv < Himg) &&
                           (u0 < WF - 1) && (v0 < HF - 1);

        const int u0c = min(max(u0, 0), WF - 2);
        const int v0c = min(max(v0, 0), HF - 2);
        s_coord[p] = u0c | (v0c << 8) | (valid ? (1 << 31) : 0);
        if (valid) atomicMin(&s_first, p);
    }
    __syncthreads();

    const int first = (s_first == P_TOT) ? 0 : s_first;

    // ---- Phase 2: gather 'stored' vector into smem (first 256 threads) ----
    if (tid < C_FEAT) {
        const int cf    = s_coord[first];
        const int u0f   = cf & 0xFF;
        const int v0f   = (cf >> 8) & 0xFF;
        const int viewf = first % N_VIEWS;
        const float* pch = feats + (size_t)viewf * C_FEAT * HW
                                 + (size_t)tid * HW
                                 + (size_t)v0f * WF + u0f;
        const float a = pch[0], b = pch[1], c = pch[WF], d = pch[WF + 1];
        const float fm = 0.25f * (a + b + c + d);
        s_stored[tid] = fm;
        s_red[tid] = fm * fm;
    }
    __syncthreads();
    #pragma unroll
    for (int s = 128; s > 0; s >>= 1) {
        if (tid < s) s_red[tid] += s_red[tid + s];
        __syncthreads();
    }
    if (tid == 0) s_sinv = 1.0f / fmaxf(sqrtf(s_red[0]), EPS);
    __syncthreads();

    // ---- Phase 3: one pair per warp, full-MLP batched loads ----
    {
        const int p  = blockIdx.x * NWARP + warp;
        const int cp    = s_coord[p];
        const int valid = cp >> 31;
        float loss = 0.0f;
        int cnt = 0;
        if (valid && p != first) {
            const int u0   = cp & 0xFF;
            const int v0   = (cp >> 8) & 0xFF;
            const int view = p % N_VIEWS;
            const float* base = feats + (size_t)view * C_FEAT * HW
                                      + (size_t)v0 * WF + u0;

            // Batch all 32 loads (4 pixels x 8 channel-groups) before any use.
            float x0[8], x1[8], x2[8], x3[8];
            #pragma unroll
            for (int i = 0; i < 8; i++) {
                const float* pch = base + (size_t)(lane + i * 32) * HW;
                x0[i] = pch[0];
                x1[i] = pch[1];
                x2[i] = pch[WF];
                x3[i] = pch[WF + 1];
            }
            float dot = 0.0f, nrm = 0.0f;
            #pragma unroll
            for (int i = 0; i < 8; i++) {
                const float fm = 0.25f * (x0[i] + x1[i] + x2[i] + x3[i]);
                dot += fm * s_stored[lane + i * 32];
                nrm += fm * fm;
            }
            #pragma unroll
            for (int o = 16; o > 0; o >>= 1) {
                dot += __shfl_xor_sync(0xffffffffu, dot, o);
                nrm += __shfl_xor_sync(0xffffffffu, nrm, o);
            }
            const float inv_i = 1.0f / fmaxf(sqrtf(nrm), EPS);
            loss = 1.0f - dot * inv_i * s_sinv;
            cnt = 1;
        }
        if (lane == 0) {
            s_loss[warp] = loss;
            s_lval[warp] = cnt;
        }
    }
    __syncthreads();

    // ---- Phase 4: deterministic block sum -> fixed-point global atomics ----
    if (tid == 0) {
        float bsum = 0.0f;
        int   bcnt = 0;
        #pragma unroll
        for (int k = 0; k < NWARP; k++) { bsum += s_loss[k]; bcnt += s_lval[k]; }
        const long long q = llrint((double)bsum * FSCALE);
        atomicAdd(&g_sum, (unsigned long long)q);
        atomicAdd(&g_cnt, bcnt);
        __threadfence();
        const int done = atomicAdd(&g_done, 1);
        if (done == NBLK - 1) {
            const long long tot = (long long)atomicAdd(&g_sum, 0ULL);
            const int n = atomicAdd(&g_cnt, 0);
            out[0] = (n > 0) ? (float)(((double)tot / FSCALE) / (double)n) : 0.0f;
            // reset for next replay (kernel boundary orders this vs next launch)
            g_sum = 0ULL; g_cnt = 0; g_done = 0;
        }
    }
}

extern "C" void kernel_launch(void* const* d_in, const int* in_sizes, int n_in,
                              void* d_out, int out_size)
{
    const float* boxes     = (const float*)d_in[0];  // (256, 7)
    const float* feats     = (const float*)d_in[1];  // (6, 256, 116, 200)
    const float* Kmat      = (const float*)d_in[2];  // (6, 3, 3)
    const float* Tmat      = (const float*)d_in[3];  // (6, 4, 4)
    const int*   img_sizes = (const int*)d_in[4];    // (6, 2)
    float* out = (float*)d_out;

    fused_kernel<<<NBLK, NTHR>>>(boxes, feats, Kmat, Tmat, img_sizes, out);
}

// round 6
// speedup vs baseline: 1.3986x; 1.3986x over previous
#include <cuda_runtime.h>
#include <math.h>

#define N_BOXES 256
#define N_VIEWS 6
#define P_TOT   (N_BOXES * N_VIEWS)   // 1536
#define C_FEAT  256
#define HF      116
#define WF      200
#define HW      (HF * WF)             // 23200
#define EPS     1e-8f

#define NBLK    148                   // one block per SM
#define NTHR    384                   // 12 warps
#define NWARP   12
#define FSCALE  4294967296.0          // 2^32 fixed-point scale

// Deterministic cross-block accumulators (integer atomics only)
__device__ unsigned long long g_sum  = 0ULL;
__device__ int                g_cnt  = 0;
__device__ int                g_done = 0;

__global__ void __launch_bounds__(NTHR, 1)
fused_kernel(const float* __restrict__ boxes,
             const float* __restrict__ feats,
             const float* __restrict__ Kmat,
             const float* __restrict__ Tmat,
             const int*   __restrict__ img_sizes,
             float*       __restrict__ out)
{
    __shared__ int   s_coord[P_TOT];      // u0c | v0c<<8 | valid<<31
    __shared__ int   s_first;
    __shared__ float s_stored[C_FEAT];
    __shared__ float s_red[256];
    __shared__ float s_sinv;
    __shared__ float s_loss[NWARP];
    __shared__ int   s_lval[NWARP];

    const int tid  = threadIdx.x;
    const int warp = tid >> 5;
    const int lane = tid & 31;

    if (tid == 0) s_first = P_TOT;
    __syncthreads();

    // ---- Phase 1: every block computes ALL projections (redundant, cheap) ----
    #pragma unroll
    for (int i = 0; i < P_TOT / NTHR; i++) {
        const int p = tid + i * NTHR;
        const int n = p / N_VIEWS;
        const int v = p - n * N_VIEWS;
        const float cx = boxes[n * 7 + 0];
        const float cy = boxes[n * 7 + 1];
        const float cz = boxes[n * 7 + 2];

        const float* Tv = Tmat + v * 16;   // 4x4 row-major
        const float pc0 = Tv[0] * cx + Tv[1] * cy + Tv[2]  * cz + Tv[3];
        const float pc1 = Tv[4] * cx + Tv[5] * cy + Tv[6]  * cz + Tv[7];
        const float pc2 = Tv[8] * cx + Tv[9] * cy + Tv[10] * cz + Tv[11];

        const float* Kv = Kmat + v * 9;    // 3x3 row-major
        const float q0 = Kv[0] * pc0 + Kv[1] * pc1 + Kv[2] * pc2;
        const float q1 = Kv[3] * pc0 + Kv[4] * pc1 + Kv[5] * pc2;
        const float q2 = Kv[6] * pc0 + Kv[7] * pc1 + Kv[8] * pc2;

        const float z  = pc2;
        const float u  = q0 / q2;          // ref: u = p2d.x / p2d.z
        const float vv = q1 / z;           // ref: v = p2d.y / p_cam.z

        const float Himg = (float)img_sizes[v * 2 + 0];
        const float Wimg = (float)img_sizes[v * 2 + 1];
        const float u_s = u  * (float)WF / Wimg;
        const float v_s = vv * (float)HF / Himg;
        const int u0 = (int)floorf(u_s);
        const int v0 = (int)floorf(v_s);

        const bool valid = (z > 0.0f) && (u >= 0.0f) && (u < Wimg) &&
                           (vv >= 0.0f) && (vv < Himg) &&
                           (u0 < WF - 1) && (v0 < HF - 1);

        const int u0c = min(max(u0, 0), WF - 2);
        const int v0c = min(max(v0, 0), HF - 2);
        s_coord[p] = u0c | (v0c << 8) | (valid ? (1 << 31) : 0);
        if (valid) atomicMin(&s_first, p);
    }
    __syncthreads();

    const int first = (s_first == P_TOT) ? 0 : s_first;

    // ---- Phase 2: gather 'stored' vector into smem (first 256 threads) ----
    if (tid < C_FEAT) {
        const int cf    = s_coord[first];
        const int u0f   = cf & 0xFF;
        const int v0f   = (cf >> 8) & 0xFF;
        const int viewf = first % N_VIEWS;
        const float* pch = feats + (size_t)viewf * C_FEAT * HW
                                 + (size_t)tid * HW
                                 + (size_t)v0f * WF + u0f;
        const float a = pch[0], b = pch[1], c = pch[WF], d = pch[WF + 1];
        const float fm = 0.25f * (a + b + c + d);
        s_stored[tid] = fm;
        s_red[tid] = fm * fm;
    }
    __syncthreads();
    #pragma unroll
    for (int s = 128; s > 0; s >>= 1) {
        if (tid < s) s_red[tid] += s_red[tid + s];
        __syncthreads();
    }
    if (tid == 0) s_sinv = 1.0f / fmaxf(sqrtf(s_red[0]), EPS);
    __syncthreads();

    // ---- Phase 3: one pair per warp, cyclic distribution over all SMs.
    // Lane remap: lanes (2j, 2j+1) load u0 / u0+1 of the same channel -> the
    // two lanes share one 128B line => 16 wavefronts per LDG instead of 32.
    {
        const int p = blockIdx.x + NBLK * warp;   // warp 0..10 active
        float loss = 0.0f;
        int cnt = 0;
        if (p < P_TOT) {
            const int cp    = s_coord[p];
            const int valid = cp >> 31;
            if (valid && p != first) {
                const int u0   = cp & 0xFF;
                const int v0   = (cp >> 8) & 0xFF;
                const int view = p % N_VIEWS;
                const int du   = lane & 1;        // 0 or 1 (u offset)
                const int chof = lane >> 1;       // 0..15
                const float* base = feats + (size_t)view * C_FEAT * HW
                                          + (size_t)v0 * WF + u0 + du;

                // Batch all 32 loads (16 channel-groups x 2 rows) for max MLP.
                float y0[16], y1[16];
                #pragma unroll
                for (int i = 0; i < 16; i++) {
                    const float* pch = base + (size_t)(chof + i * 16) * HW;
                    y0[i] = pch[0];      // row v0
                    y1[i] = pch[WF];     // row v0+1
                }
                float dot = 0.0f, nrm = 0.0f;
                #pragma unroll
                for (int i = 0; i < 16; i++) {
                    const int c = chof + i * 16;
                    const float s2 = y0[i] + y1[i];                 // this du
                    const float sp = __shfl_xor_sync(0xffffffffu, s2, 1); // other du
                    const float fm = 0.25f * (s2 + sp);             // full bilinear avg
                    dot += fm * s_stored[c];
                    nrm += fm * fm;
                }
                // Each channel counted twice (both lanes of a pair) -> halve after.
                #pragma unroll
                for (int o = 16; o > 0; o >>= 1) {
                    dot += __shfl_xor_sync(0xffffffffu, dot, o);
                    nrm += __shfl_xor_sync(0xffffffffu, nrm, o);
                }
                dot *= 0.5f;
                nrm *= 0.5f;
                const float inv_i = 1.0f / fmaxf(sqrtf(nrm), EPS);
                loss = 1.0f - dot * inv_i * s_sinv;
                cnt = 1;
            }
        }
        if (lane == 0) {
            s_loss[warp] = loss;
            s_lval[warp] = cnt;
        }
    }
    __syncthreads();

    // ---- Phase 4: deterministic block sum -> fixed-point global atomics ----
    if (tid == 0) {
        float bsum = 0.0f;
        int   bcnt = 0;
        #pragma unroll
        for (int k = 0; k < NWARP; k++) { bsum += s_loss[k]; bcnt += s_lval[k]; }
        const long long q = llrint((double)bsum * FSCALE);
        atomicAdd(&g_sum, (unsigned long long)q);
        atomicAdd(&g_cnt, bcnt);
        __threadfence();
        const int done = atomicAdd(&g_done, 1);
        if (done == NBLK - 1) {
            const long long tot = (long long)atomicAdd(&g_sum, 0ULL);
            const int n = atomicAdd(&g_cnt, 0);
            out[0] = (n > 0) ? (float)(((double)tot / FSCALE) / (double)n) : 0.0f;
            // reset for next replay (kernel boundary orders this vs next launch)
            g_sum = 0ULL; g_cnt = 0; g_done = 0;
        }
    }
}

extern "C" void kernel_launch(void* const* d_in, const int* in_sizes, int n_in,
                              void* d_out, int out_size)
{
    const float* boxes     = (const float*)d_in[0];  // (256, 7)
    const float* feats     = (const float*)d_in[1];  // (6, 256, 116, 200)
    const float* Kmat      = (const float*)d_in[2];  // (6, 3, 3)
    const float* Tmat      = (const float*)d_in[3];  // (6, 4, 4)
    const int*   img_sizes = (const int*)d_in[4];    // (6, 2)
    float* out = (float*)d_out;

    fused_kernel<<<NBLK, NTHR>>>(boxes, feats, Kmat, Tmat, img_sizes, out);
}